// round 1
// baseline (speedup 1.0000x reference)
#include <cuda_runtime.h>
#include <cstdint>

#define N_PTS 4096
#define DIM 128
#define TOPK 4
#define ROWS_PER_BLOCK 16
#define THREADS 512   // 16 warps, one warp per row

// Dynamic smem layout:
//   float4 pos_s[4096]        65536 B
//   float4 W_s[128*32]        65536 B   (W[d][o], float4 over o)
//   float  bias_s[128]          512 B
//   float  y_s[16*128]         8192 B
// total                      139776 B

__global__ void __launch_bounds__(THREADS, 1)
gnn_topk_agg_linear(const float* __restrict__ x,
                    const float* __restrict__ pos,
                    const float* __restrict__ W,
                    const float* __restrict__ bias,
                    float* __restrict__ out)
{
    extern __shared__ float smem[];
    float4* pos_s  = (float4*)smem;                 // 4096 float4
    float4* W_s    = pos_s + N_PTS;                 // 4096 float4
    float*  bias_s = (float*)(W_s + DIM * 32);      // 128 floats
    float*  y_s    = bias_s + DIM;                  // 16*128 floats

    const int tid = threadIdx.x;
    const int g0  = blockIdx.x * ROWS_PER_BLOCK;    // first global row of block
    const int b   = g0 >> 12;                       // batch (4096 rows per batch)

    // ---- cooperative loads: pos (this batch), W, bias ----
    const float* pb = pos + (size_t)b * N_PTS * 3;
    for (int n = tid; n < N_PTS; n += THREADS) {
        float4 p;
        p.x = pb[n * 3 + 0];
        p.y = pb[n * 3 + 1];
        p.z = pb[n * 3 + 2];
        p.w = 0.0f;
        pos_s[n] = p;
    }
    const float4* W4 = (const float4*)W;
    for (int i = tid; i < DIM * 32; i += THREADS) W_s[i] = W4[i];
    if (tid < DIM) bias_s[tid] = bias[tid];
    __syncthreads();

    const int warp = tid >> 5;
    const int lane = tid & 31;
    const int g    = g0 + warp;          // global row
    const int n    = g & (N_PTS - 1);    // row within batch

    // ---- phase 1: per-lane top-4 smallest squared distances ----
    const float4 pi = pos_s[n];
    unsigned long long k0 = ~0ull, k1 = ~0ull, k2 = ~0ull, k3 = ~0ull;
    #pragma unroll 4
    for (int j = lane; j < N_PTS; j += 32) {
        float4 pj = pos_s[j];
        float dx = pi.x - pj.x;
        float dy = pi.y - pj.y;
        float dz = pi.z - pj.z;
        float d2 = fmaf(dz, dz, fmaf(dy, dy, dx * dx));
        // key: (d2 bits, j). d2 >= 0 so float-bit compare == float compare.
        unsigned long long key =
            ((unsigned long long)__float_as_uint(d2) << 32) | (unsigned)j;
        if (key < k3) {
            k3 = key;
            if (k3 < k2) { unsigned long long t = k2; k2 = k3; k3 = t; }
            if (k2 < k1) { unsigned long long t = k1; k1 = k2; k2 = t; }
            if (k1 < k0) { unsigned long long t = k0; k0 = k1; k1 = t; }
        }
    }

    // ---- phase 2: warp merge (4 rounds of u64 min-reduce; keys are unique) ----
    float  wgt[TOPK];
    int    idx[TOPK];
    #pragma unroll
    for (int r = 0; r < TOPK; r++) {
        unsigned long long v = k0;
        #pragma unroll
        for (int off = 16; off; off >>= 1) {
            unsigned long long o = __shfl_xor_sync(0xffffffffu, v, off);
            v = (o < v) ? o : v;
        }
        if (k0 == v) { k0 = k1; k1 = k2; k2 = k3; k3 = ~0ull; }
        float d2 = __uint_as_float((unsigned)(v >> 32));
        idx[r]   = (int)(v & 0xffffffffull);
        wgt[r]   = expf(-0.5f * (d2 + 1e-8f));   // adj value
    }
    float denom = ((wgt[0] + wgt[1]) + wgt[2]) + wgt[3] + 1e-8f;
    float inv = 1.0f / denom;
    #pragma unroll
    for (int r = 0; r < TOPK; r++) wgt[r] *= inv;

    // ---- phase 3: weighted aggregation y = sum_r w_r * x[b, j_r, :] ----
    const float4* x4 = (const float4*)x;
    const size_t xbase = (size_t)b * N_PTS * 32;  // float4 units
    float4 acc = make_float4(0.f, 0.f, 0.f, 0.f);
    #pragma unroll
    for (int r = 0; r < TOPK; r++) {
        float4 xv = x4[xbase + (size_t)idx[r] * 32 + lane];
        acc.x = fmaf(wgt[r], xv.x, acc.x);
        acc.y = fmaf(wgt[r], xv.y, acc.y);
        acc.z = fmaf(wgt[r], xv.z, acc.z);
        acc.w = fmaf(wgt[r], xv.w, acc.w);
    }
    float4* yrow4 = (float4*)(y_s + warp * DIM);
    yrow4[lane] = acc;
    __syncwarp();

    // ---- phase 4: fused linear  out = y @ W + b ----
    const float* yr = y_s + warp * DIM;
    float4 o = ((const float4*)bias_s)[lane];
    #pragma unroll 4
    for (int d = 0; d < DIM; d++) {
        float  yd = yr[d];                 // smem broadcast
        float4 wv = W_s[d * 32 + lane];    // conflict-free LDS.128
        o.x = fmaf(yd, wv.x, o.x);
        o.y = fmaf(yd, wv.y, o.y);
        o.z = fmaf(yd, wv.z, o.z);
        o.w = fmaf(yd, wv.w, o.w);
    }
    ((float4*)out)[(size_t)g * 32 + lane] = o;
}

extern "C" void kernel_launch(void* const* d_in, const int* in_sizes, int n_in,
                              void* d_out, int out_size)
{
    const float* x    = (const float*)d_in[0];
    const float* pos  = (const float*)d_in[1];
    const float* W    = (const float*)d_in[2];
    const float* bias = (const float*)d_in[3];
    float* out        = (float*)d_out;

    const int rows   = in_sizes[1] / 3;            // B * N
    const int blocks = rows / ROWS_PER_BLOCK;      // 512

    const size_t smem = (size_t)N_PTS * 16          // pos_s
                      + (size_t)DIM * 32 * 16       // W_s
                      + (size_t)DIM * 4             // bias_s
                      + (size_t)ROWS_PER_BLOCK * DIM * 4;  // y_s

    cudaFuncSetAttribute(gnn_topk_agg_linear,
                         cudaFuncAttributeMaxDynamicSharedMemorySize, (int)smem);
    gnn_topk_agg_linear<<<blocks, THREADS, smem>>>(x, pos, W, bias, out);
}

// round 2
// speedup vs baseline: 1.3101x; 1.3101x over previous
#include <cuda_runtime.h>
#include <cstdint>

#define N_PTS   4096
#define DIM     128
#define TOPK    4

// ---------------- Z = x @ W  (precomputed, 8192x128 @ 128x128) ----------------
__device__ float Z_buf[2 * N_PTS * DIM];   // 4 MB scratch

#define GA_THREADS 256
#define GA_ROWS    32          // rows per block; 8 warps x 4 rows

__global__ void __launch_bounds__(GA_THREADS, 2)
gemm_xw(const float* __restrict__ x, const float* __restrict__ W)
{
    extern __shared__ float smemA[];
    float4* W_s = (float4*)smemA;             // 128*32 float4 = 64 KB  (W[d][o])
    float*  x_s = (float*)(W_s + DIM * 32);   // 32*128 floats = 16 KB

    const int tid = threadIdx.x;
    const int g0  = blockIdx.x * GA_ROWS;

    const float4* W4 = (const float4*)W;
    #pragma unroll
    for (int i = tid; i < DIM * 32; i += GA_THREADS) W_s[i] = W4[i];

    const float4* xg = (const float4*)x + (size_t)g0 * 32;
    float4* xs4 = (float4*)x_s;
    #pragma unroll
    for (int i = tid; i < GA_ROWS * 32; i += GA_THREADS) xs4[i] = xg[i];
    __syncthreads();

    const int warp = tid >> 5;
    const int lane = tid & 31;
    const float* xr = x_s + warp * 4 * DIM;   // 4 rows per warp

    float4 a0 = make_float4(0.f,0.f,0.f,0.f);
    float4 a1 = a0, a2 = a0, a3 = a0;

    #pragma unroll 4
    for (int d = 0; d < DIM; d++) {
        float4 wv = W_s[d * 32 + lane];       // conflict-free LDS.128
        float y0 = xr[d];                      // smem broadcasts
        float y1 = xr[d + DIM];
        float y2 = xr[d + 2*DIM];
        float y3 = xr[d + 3*DIM];
        a0.x = fmaf(y0, wv.x, a0.x); a0.y = fmaf(y0, wv.y, a0.y);
        a0.z = fmaf(y0, wv.z, a0.z); a0.w = fmaf(y0, wv.w, a0.w);
        a1.x = fmaf(y1, wv.x, a1.x); a1.y = fmaf(y1, wv.y, a1.y);
        a1.z = fmaf(y1, wv.z, a1.z); a1.w = fmaf(y1, wv.w, a1.w);
        a2.x = fmaf(y2, wv.x, a2.x); a2.y = fmaf(y2, wv.y, a2.y);
        a2.z = fmaf(y2, wv.z, a2.z); a2.w = fmaf(y2, wv.w, a2.w);
        a3.x = fmaf(y3, wv.x, a3.x); a3.y = fmaf(y3, wv.y, a3.y);
        a3.z = fmaf(y3, wv.z, a3.z); a3.w = fmaf(y3, wv.w, a3.w);
    }

    float4* Z4 = (float4*)Z_buf;
    const size_t r = (size_t)g0 + warp * 4;
    Z4[(r + 0) * 32 + lane] = a0;
    Z4[(r + 1) * 32 + lane] = a1;
    Z4[(r + 2) * 32 + lane] = a2;
    Z4[(r + 3) * 32 + lane] = a3;
}

// --------- top-4 neighbor scan + normalized gather of Z + bias ----------
#define GB_THREADS 512
#define GB_ROWS    32          // 16 warps x 2 rows

__global__ void __launch_bounds__(GB_THREADS, 2)
topk_gather(const float* __restrict__ pos,
            const float* __restrict__ bias,
            float* __restrict__ out)
{
    extern __shared__ float4 pos_s[];          // 4096 float4 = 64 KB

    const int tid = threadIdx.x;
    const int g0  = blockIdx.x * GB_ROWS;
    const int b   = g0 >> 12;                  // batch

    const float* pb = pos + (size_t)b * N_PTS * 3;
    for (int n = tid; n < N_PTS; n += GB_THREADS) {
        float4 p;
        p.x = pb[n * 3 + 0];
        p.y = pb[n * 3 + 1];
        p.z = pb[n * 3 + 2];
        p.w = 0.0f;
        pos_s[n] = p;
    }
    __syncthreads();

    const int warp = tid >> 5;
    const int lane = tid & 31;
    const int r0   = g0 + warp * 2;            // two rows per warp
    const int n0   = r0 & (N_PTS - 1);
    const int n1   = n0 + 1;

    const float4 p0 = pos_s[n0];
    const float4 p1 = pos_s[n1];

    const float INF = __int_as_float(0x7f800000);
    float d00=INF,d01=INF,d02=INF,d03=INF;  int j00=0,j01=0,j02=0,j03=0;
    float d10=INF,d11=INF,d12=INF,d13=INF;  int j10=0,j11=0,j12=0,j13=0;

    #pragma unroll 2
    for (int j = lane; j < N_PTS; j += 32) {
        float4 pj = pos_s[j];
        float ax = p0.x - pj.x, ay = p0.y - pj.y, az = p0.z - pj.z;
        float e0 = fmaf(az, az, fmaf(ay, ay, ax * ax));
        float bx = p1.x - pj.x, by = p1.y - pj.y, bz = p1.z - pj.z;
        float e1 = fmaf(bz, bz, fmaf(by, by, bx * bx));

        if (e0 < d03) {                         // rare
            d03 = e0; j03 = j;
            if (e0 < d02) { d03=d02; j03=j02; d02=e0; j02=j;
                if (e0 < d01) { d02=d01; j02=j01; d01=e0; j01=j;
                    if (e0 < d00) { d01=d00; j01=j00; d00=e0; j00=j; } } }
        }
        if (e1 < d13) {                         // rare
            d13 = e1; j13 = j;
            if (e1 < d12) { d13=d12; j13=j12; d12=e1; j12=j;
                if (e1 < d11) { d12=d11; j12=j11; d11=e1; j11=j;
                    if (e1 < d10) { d11=d10; j11=j10; d10=e1; j10=j; } } }
        }
    }

    // ---- warp merge per row (exact tie-break via u64 (d2_bits, j) keys) ----
    unsigned long long ka0, ka1, ka2, ka3;
    float  wgt[2][TOPK];
    int    idx[2][TOPK];

    #pragma unroll
    for (int row = 0; row < 2; row++) {
        if (row == 0) {
            ka0 = ((unsigned long long)__float_as_uint(d00) << 32) | (unsigned)j00;
            ka1 = ((unsigned long long)__float_as_uint(d01) << 32) | (unsigned)j01;
            ka2 = ((unsigned long long)__float_as_uint(d02) << 32) | (unsigned)j02;
            ka3 = ((unsigned long long)__float_as_uint(d03) << 32) | (unsigned)j03;
        } else {
            ka0 = ((unsigned long long)__float_as_uint(d10) << 32) | (unsigned)j10;
            ka1 = ((unsigned long long)__float_as_uint(d11) << 32) | (unsigned)j11;
            ka2 = ((unsigned long long)__float_as_uint(d12) << 32) | (unsigned)j12;
            ka3 = ((unsigned long long)__float_as_uint(d13) << 32) | (unsigned)j13;
        }
        #pragma unroll
        for (int r = 0; r < TOPK; r++) {
            unsigned long long v = ka0;
            #pragma unroll
            for (int off = 16; off; off >>= 1) {
                unsigned long long o = __shfl_xor_sync(0xffffffffu, v, off);
                v = (o < v) ? o : v;
            }
            if (ka0 == v) { ka0 = ka1; ka1 = ka2; ka2 = ka3; ka3 = ~0ull; }
            float d2    = __uint_as_float((unsigned)(v >> 32));
            idx[row][r] = (int)(v & 0xffffffffull);
            wgt[row][r] = expf(-0.5f * (d2 + 1e-8f));
        }
        float denom = ((wgt[row][0] + wgt[row][1]) + wgt[row][2]) + wgt[row][3] + 1e-8f;
        float inv = 1.0f / denom;
        #pragma unroll
        for (int r = 0; r < TOPK; r++) wgt[row][r] *= inv;
    }

    // ---- gather Z rows (L2 resident), add bias, store ----
    const float4* Z4 = (const float4*)Z_buf + (size_t)b * N_PTS * 32;
    const float4  bv = ((const float4*)bias)[lane];
    float4* out4 = (float4*)out;

    #pragma unroll
    for (int row = 0; row < 2; row++) {
        float4 acc = bv;
        #pragma unroll
        for (int r = 0; r < TOPK; r++) {
            float  w  = wgt[row][r];
            float4 zv = Z4[(size_t)idx[row][r] * 32 + lane];
            acc.x = fmaf(w, zv.x, acc.x);
            acc.y = fmaf(w, zv.y, acc.y);
            acc.z = fmaf(w, zv.z, acc.z);
            acc.w = fmaf(w, zv.w, acc.w);
        }
        out4[(size_t)(r0 + row) * 32 + lane] = acc;
    }
}

extern "C" void kernel_launch(void* const* d_in, const int* in_sizes, int n_in,
                              void* d_out, int out_size)
{
    const float* x    = (const float*)d_in[0];
    const float* pos  = (const float*)d_in[1];
    const float* W    = (const float*)d_in[2];
    const float* bias = (const float*)d_in[3];
    float* out        = (float*)d_out;

    const int rows = in_sizes[1] / 3;                  // B * N = 8192

    // Kernel A: Z = x @ W
    const size_t smemA = (size_t)DIM * 32 * 16 + (size_t)GA_ROWS * DIM * 4;  // 80 KB
    cudaFuncSetAttribute(gemm_xw, cudaFuncAttributeMaxDynamicSharedMemorySize, (int)smemA);
    gemm_xw<<<rows / GA_ROWS, GA_THREADS, smemA>>>(x, W);

    // Kernel B: top-4 + normalized gather + bias
    const size_t smemB = (size_t)N_PTS * 16;           // 64 KB
    cudaFuncSetAttribute(topk_gather, cudaFuncAttributeMaxDynamicSharedMemorySize, (int)smemB);
    topk_gather<<<rows / GB_ROWS, GB_THREADS, smemB>>>(pos, bias, out);
}